// round 1
// baseline (speedup 1.0000x reference)
#include <cuda_runtime.h>
#include <math.h>

#define BATCH   2
#define SEQ     960
#define NHEADS  32
#define HDIM    128
#define HID     4096
#define MTOT    (BATCH*SEQ)     // 1920
#define NBLK    15              // 960 / 64 token-blocks
#define BHTOT   (BATCH*NHEADS)  // 64
#define NEGF    (-3.4028234663852886e38f)

// ---------------- scratch (static device globals; no allocation) ----------------
__device__ float g_q[(size_t)BHTOT*SEQ*HDIM];   // [b,h,q,d]  30 MB
__device__ float g_k[(size_t)BHTOT*SEQ*HDIM];
__device__ float g_v[(size_t)BHTOT*SEQ*HDIM];
__device__ float g_s[(size_t)BHTOT*SEQ*SEQ];    // scores/probs [b,h,q,k] 236 MB
__device__ float g_o[(size_t)MTOT*HID];         // attn out pre-Wo [b,q,h*d]

// ---------------- generic 128x128x16 fp32 SGEMM ----------------
// MODE 0: C = Cparam plain row-major  (optionally A = g_o via asrc)
// MODE 1: headed store: C(m,n) -> dstbuf[((b*32+h)*SEQ+pos)*128+d]
template<int MODE>
__global__ __launch_bounds__(256)
void sgemm128(const float* __restrict__ Aparam, const float* __restrict__ B,
              float* __restrict__ Cparam, int asrc, int dst, int M, int N, int K)
{
    const float* A = asrc ? (const float*)g_o : Aparam;
    __shared__ float As[16][132];   // padded: conflict-free transposed stores
    __shared__ float Bs[16][128];
    const int tid = threadIdx.x;
    const int m0 = blockIdx.y * 128;
    const int n0 = blockIdx.x * 128;
    const int tx = tid & 15, ty = tid >> 4;

    float acc[8][8];
    #pragma unroll
    for (int i = 0; i < 8; i++)
        #pragma unroll
        for (int j = 0; j < 8; j++) acc[i][j] = 0.f;

    for (int k0 = 0; k0 < K; k0 += 16) {
        #pragma unroll
        for (int i = 0; i < 2; i++) {               // A tile: 128x16 (512 float4)
            int slot = tid + i * 256;
            int row = slot >> 2;
            int c4  = slot & 3;
            float4 v = *(const float4*)&A[(size_t)(m0 + row) * K + k0 + c4 * 4];
            As[c4*4+0][row] = v.x;
            As[c4*4+1][row] = v.y;
            As[c4*4+2][row] = v.z;
            As[c4*4+3][row] = v.w;
        }
        #pragma unroll
        for (int i = 0; i < 2; i++) {               // B tile: 16x128 (512 float4)
            int slot = tid + i * 256;
            int row = slot >> 5;
            int c4  = slot & 31;
            *(float4*)&Bs[row][c4*4] =
                *(const float4*)&B[(size_t)(k0 + row) * N + n0 + c4 * 4];
        }
        __syncthreads();
        #pragma unroll
        for (int kk = 0; kk < 16; kk++) {
            float ra[8], rb[8];
            *(float4*)&ra[0] = *(const float4*)&As[kk][ty*8];
            *(float4*)&ra[4] = *(const float4*)&As[kk][ty*8+4];
            *(float4*)&rb[0] = *(const float4*)&Bs[kk][tx*8];
            *(float4*)&rb[4] = *(const float4*)&Bs[kk][tx*8+4];
            #pragma unroll
            for (int i = 0; i < 8; i++)
                #pragma unroll
                for (int j = 0; j < 8; j++)
                    acc[i][j] = fmaf(ra[i], rb[j], acc[i][j]);
        }
        __syncthreads();
    }

    #pragma unroll
    for (int i = 0; i < 8; i++) {
        int m = m0 + ty * 8 + i;
        if (MODE == 0) {
            *(float4*)&Cparam[(size_t)m * N + n0 + tx*8]     = *(float4*)&acc[i][0];
            *(float4*)&Cparam[(size_t)m * N + n0 + tx*8 + 4] = *(float4*)&acc[i][4];
        } else {
            float* dbuf = (dst == 0) ? g_q : (dst == 1) ? g_k : g_v;
            int b = m / SEQ, pos = m % SEQ;
            #pragma unroll
            for (int j = 0; j < 8; j += 4) {
                int n = n0 + tx * 8 + j;
                int h = n >> 7, d = n & 127;  // n%128 multiple of 4; h const over j..j+3
                *(float4*)&dbuf[((size_t)(b * NHEADS + h) * SEQ + pos) * HDIM + d]
                    = *(float4*)&acc[i][j];
            }
        }
    }
}

// ---------------- RoPE on q (with 1/sqrt(128) fold) and k ----------------
__global__ __launch_bounds__(128)
void rope_kernel()
{
    int pos = blockIdx.x;
    int bh  = blockIdx.y;
    int d   = threadIdx.x;
    size_t base = ((size_t)bh * SEQ + pos) * HDIM;
    __shared__ float sq[HDIM], sk[HDIM];
    sq[d] = g_q[base + d];
    sk[d] = g_k[base + d];
    __syncthreads();
    int i = d & 63;
    // inv_freq = 10000^(-i/64)
    float inv = expf(-(float)i * (9.210340371976184f / 64.f));
    float ang = (float)pos * inv;
    float c = cosf(ang), s = sinf(ang);
    float rq = (d < 64) ? -sq[d + 64] : sq[d - 64];
    float rk = (d < 64) ? -sk[d + 64] : sk[d - 64];
    const float qscale = 0.08838834764831845f;  // 1/sqrt(128)
    g_q[base + d] = (sq[d] * c + rq * s) * qscale;
    g_k[base + d] = sk[d] * c + rk * s;
}

// ---------------- scores: S = Qr @ Kr^T per (b,h), lower-triangular tiles ----------------
__global__ __launch_bounds__(256)
void scores_kernel()
{
    int kt = blockIdx.x, qt = blockIdx.y, bh = blockIdx.z;
    int q0 = qt * 64, k0 = kt * 64;
    if (k0 > q0 + 63) return;   // fully non-causal tile: softmax masks by index
    const float* Q = g_q + (size_t)bh * SEQ * HDIM;
    const float* K = g_k + (size_t)bh * SEQ * HDIM;
    float*       S = g_s + (size_t)bh * SEQ * SEQ;
    __shared__ float Qs[64][65], Ks[64][65];
    int tid = threadIdx.x;
    int tx = tid & 15, ty = tid >> 4;
    float acc[4][4];
    #pragma unroll
    for (int i = 0; i < 4; i++)
        #pragma unroll
        for (int j = 0; j < 4; j++) acc[i][j] = 0.f;

    for (int c = 0; c < 2; c++) {               // K-dim in 2 chunks of 64
        #pragma unroll
        for (int i = 0; i < 4; i++) {           // 64x64 floats = 1024 float4
            int slot = tid + i * 256;
            int row = slot >> 4;
            int c4  = slot & 15;
            float4 v = *(const float4*)&Q[(size_t)(q0 + row) * HDIM + c * 64 + c4 * 4];
            Qs[row][c4*4+0]=v.x; Qs[row][c4*4+1]=v.y; Qs[row][c4*4+2]=v.z; Qs[row][c4*4+3]=v.w;
            float4 w = *(const float4*)&K[(size_t)(k0 + row) * HDIM + c * 64 + c4 * 4];
            Ks[row][c4*4+0]=w.x; Ks[row][c4*4+1]=w.y; Ks[row][c4*4+2]=w.z; Ks[row][c4*4+3]=w.w;
        }
        __syncthreads();
        #pragma unroll
        for (int kk = 0; kk < 64; kk++) {
            float rq[4], rk[4];
            #pragma unroll
            for (int i = 0; i < 4; i++) rq[i] = Qs[ty*4+i][kk];
            #pragma unroll
            for (int j = 0; j < 4; j++) rk[j] = Ks[tx*4+j][kk];
            #pragma unroll
            for (int i = 0; i < 4; i++)
                #pragma unroll
                for (int j = 0; j < 4; j++)
                    acc[i][j] = fmaf(rq[i], rk[j], acc[i][j]);
        }
        __syncthreads();
    }
    #pragma unroll
    for (int i = 0; i < 4; i++)
        #pragma unroll
        for (int j = 0; j < 4; j++)
            S[(size_t)(q0 + ty*4 + i) * SEQ + k0 + tx*4 + j] = acc[i][j];
}

// ---------------- landmark grouped softmax, in place on g_s ----------------
// Row q, block B=q/64. Element k=j*64+t: group = (j==B || t==63) ? 15 : j.
// Final weight: j==B -> p ; landmark of other block -> 0 ; else p * p15(landmark_j).
__global__ __launch_bounds__(64)
void lsoftmax_kernel()
{
    int q  = blockIdx.x;
    int bh = blockIdx.y;
    float* row = g_s + ((size_t)bh * SEQ + q) * SEQ;
    int t  = threadIdx.x;
    int Bq = q >> 6;

    __shared__ float sred[64][17];
    __shared__ float gm[16], gs[16], lm[16];

    float vals[NBLK];
    #pragma unroll
    for (int j = 0; j < NBLK; j++) {
        int k = j * 64 + t;
        vals[j] = (k <= q) ? row[k] : NEGF;     // causal mask by index
    }

    // ---- per-group max: each (j,t) element belongs to exactly one group ----
    #pragma unroll
    for (int j = 0; j < NBLK; j++)
        sred[t][j] = (t != 63 && j != Bq) ? vals[j] : NEGF;
    {
        float c15;
        if (t == 63) {
            c15 = NEGF;
            #pragma unroll
            for (int j = 0; j < NBLK; j++) c15 = fmaxf(c15, vals[j]);
        } else c15 = vals[Bq];
        sred[t][15] = c15;
    }
    __syncthreads();
    if (t < 16) {
        float m = NEGF;
        for (int i = 0; i < 64; i++) m = fmaxf(m, sred[i][t]);
        gm[t] = m;
    }
    __syncthreads();

    // ---- exp + per-group sum ----
    float e[NBLK];
    #pragma unroll
    for (int j = 0; j < NBLK; j++) {
        int grp = (j == Bq || t == 63) ? 15 : j;
        e[j] = expf(vals[j] - gm[grp]);         // all-NEG group -> exp(0)=1 (matches ref)
    }
    #pragma unroll
    for (int j = 0; j < NBLK; j++)
        sred[t][j] = (t != 63 && j != Bq) ? e[j] : 0.f;
    {
        float s15;
        if (t == 63) {
            s15 = 0.f;
            #pragma unroll
            for (int j = 0; j < NBLK; j++) s15 += e[j];
        } else s15 = e[Bq];
        sred[t][15] = s15;
    }
    __syncthreads();
    if (t < 16) {
        float s = 0.f;
        for (int i = 0; i < 64; i++) s += sred[i][t];
        gs[t] = s;
    }
    __syncthreads();

    // ---- probs; landmark probs (thread 63's elements are all group-15) ----
    float p[NBLK];
    #pragma unroll
    for (int j = 0; j < NBLK; j++) {
        int grp = (j == Bq || t == 63) ? 15 : j;
        p[j] = e[j] / gs[grp];
    }
    if (t == 63) {
        #pragma unroll
        for (int j = 0; j < NBLK; j++) lm[j] = p[j];  // p15 of landmark of block j
    }
    __syncthreads();

    // ---- final weights ----
    #pragma unroll
    for (int j = 0; j < NBLK; j++) {
        int k = j * 64 + t;
        float w;
        if (j == Bq)        w = p[j];           // current block (incl. its landmark)
        else if (t == 63)   w = 0.f;            // other blocks' landmarks: mult 0
        else                w = p[j] * lm[j];   // prior/future block member
        row[k] = w;
    }
}

// ---------------- PV: O = P @ V per (b,h); store as [b,q,h*128+d] ----------------
__global__ __launch_bounds__(256)
void pv_kernel()
{
    int qt = blockIdx.x, bh = blockIdx.y;
    int q0 = qt * 64;
    const float* P = g_s + (size_t)bh * SEQ * SEQ;
    const float* V = g_v + (size_t)bh * SEQ * HDIM;
    __shared__ float Ps[64][33];
    __shared__ float Vs[32][128];
    int tid = threadIdx.x, tx = tid & 15, ty = tid >> 4;
    float acc[4][8];
    #pragma unroll
    for (int i = 0; i < 4; i++)
        #pragma unroll
        for (int j = 0; j < 8; j++) acc[i][j] = 0.f;

    for (int k0 = 0; k0 < SEQ; k0 += 32) {
        #pragma unroll
        for (int i = 0; i < 2; i++) {           // P tile 64x32 = 512 float4
            int slot = tid + i * 256;
            int row = slot >> 3;
            int c4  = slot & 7;
            float4 v = *(const float4*)&P[(size_t)(q0 + row) * SEQ + k0 + c4 * 4];
            Ps[row][c4*4+0]=v.x; Ps[row][c4*4+1]=v.y; Ps[row][c4*4+2]=v.z; Ps[row][c4*4+3]=v.w;
        }
        #pragma unroll
        for (int i = 0; i < 4; i++) {           // V tile 32x128 = 1024 float4
            int slot = tid + i * 256;
            int row = slot >> 5;
            int c4  = slot & 31;
            *(float4*)&Vs[row][c4*4] = *(const float4*)&V[(size_t)(k0 + row) * HDIM + c4 * 4];
        }
        __syncthreads();
        #pragma unroll
        for (int kk = 0; kk < 32; kk++) {
            float rp[4], rv[8];
            #pragma unroll
            for (int i = 0; i < 4; i++) rp[i] = Ps[ty*4+i][kk];
            *(float4*)&rv[0] = *(const float4*)&Vs[kk][tx*8];
            *(float4*)&rv[4] = *(const float4*)&Vs[kk][tx*8+4];
            #pragma unroll
            for (int i = 0; i < 4; i++)
                #pragma unroll
                for (int j = 0; j < 8; j++)
                    acc[i][j] = fmaf(rp[i], rv[j], acc[i][j]);
        }
        __syncthreads();
    }
    int b = bh >> 5, h = bh & 31;
    #pragma unroll
    for (int i = 0; i < 4; i++) {
        int qq = q0 + ty * 4 + i;
        size_t obase = ((size_t)(b * SEQ + qq)) * HID + h * HDIM + tx * 8;
        *(float4*)&g_o[obase]     = *(float4*)&acc[i][0];
        *(float4*)&g_o[obase + 4] = *(float4*)&acc[i][4];
    }
}

// ---------------- launch ----------------
extern "C" void kernel_launch(void* const* d_in, const int* in_sizes, int n_in,
                              void* d_out, int out_size)
{
    const float* X  = (const float*)d_in[0];
    const float* wq = (const float*)d_in[1];
    const float* wk = (const float*)d_in[2];
    const float* wv = (const float*)d_in[3];
    const float* wo = (const float*)d_in[4];
    float* out = (float*)d_out;

    dim3 gp(HID / 128, MTOT / 128);   // (32, 15)

    sgemm128<1><<<gp, 256>>>(X, wq, nullptr, 0, 0, MTOT, HID, HID);   // -> g_q
    sgemm128<1><<<gp, 256>>>(X, wk, nullptr, 0, 1, MTOT, HID, HID);   // -> g_k
    sgemm128<1><<<gp, 256>>>(X, wv, nullptr, 0, 2, MTOT, HID, HID);   // -> g_v
    rope_kernel<<<dim3(SEQ, BHTOT), 128>>>();
    scores_kernel<<<dim3(NBLK, NBLK, BHTOT), 256>>>();
    lsoftmax_kernel<<<dim3(SEQ, BHTOT), 64>>>();
    pv_kernel<<<dim3(NBLK, BHTOT), 256>>>();
    sgemm128<0><<<gp, 256>>>(nullptr, wo, out, 1, 0, MTOT, HID, HID); // g_o @ wo -> out
}

// round 5
// speedup vs baseline: 2.3332x; 2.3332x over previous
#include <cuda_runtime.h>
#include <math.h>

#define BATCH   2
#define SEQ     960
#define NHEADS  32
#define HDIM    128
#define HID     4096
#define MTOT    (BATCH*SEQ)     // 1920
#define NBLK    15
#define BHTOT   (BATCH*NHEADS)  // 64
#define NEGF    (-3.4028234663852886e38f)

// ---------------- scratch ----------------
__device__ float g_q[(size_t)BHTOT*SEQ*HDIM];
__device__ float g_k[(size_t)BHTOT*SEQ*HDIM];
__device__ float g_v[(size_t)BHTOT*SEQ*HDIM];
__device__ float g_s[(size_t)BHTOT*SEQ*SEQ];
__device__ float g_o[(size_t)MTOT*HID];

// ---------------- tf32 helpers ----------------
__device__ __forceinline__ unsigned f2tf(float f) {
    unsigned u;
    asm("cvt.rna.tf32.f32 %0, %1;" : "=r"(u) : "f"(f));
    return u;
}
__device__ __forceinline__ void mma_tf32(float* c, const unsigned* a, const unsigned* b) {
    asm volatile(
        "mma.sync.aligned.m16n8k8.row.col.f32.tf32.tf32.f32 "
        "{%0,%1,%2,%3}, {%4,%5,%6,%7}, {%8,%9}, {%0,%1,%2,%3};"
        : "+f"(c[0]), "+f"(c[1]), "+f"(c[2]), "+f"(c[3])
        : "r"(a[0]), "r"(a[1]), "r"(a[2]), "r"(a[3]), "r"(b[0]), "r"(b[1]));
}

// ---------------- tf32 GEMM 128x128x32, 8 warps (4x2), warp tile 32x64 ----------------
// M=1920, N=4096, K=4096.
// MODE 0: C row-major -> Cparam (A = g_o when asrc)
// MODE 1: headed store -> g_q/g_k/g_v ; head h == blockIdx.x (BN==HDIM)
#define ASTRIDE 36
#define BSTRIDE 136
#define A_ELEMS (128*ASTRIDE)   // 4608
#define B_ELEMS (32*BSTRIDE)    // 4352
#define TG_SMEM ((2*A_ELEMS + 2*B_ELEMS)*4)

template<int MODE>
__global__ __launch_bounds__(256, 1)
void tgemm(const float* __restrict__ Aparam, const float* __restrict__ B,
           float* __restrict__ Cparam, int asrc, int dst)
{
    const float* A = asrc ? (const float*)g_o : Aparam;
    extern __shared__ unsigned sm[];
    unsigned* As = sm;                 // [2][128][36]
    unsigned* Bs = sm + 2 * A_ELEMS;   // [2][32][136]

    const int tid  = threadIdx.x;
    const int lane = tid & 31;
    const int w    = tid >> 5;
    const int warp_m = w >> 1;          // 0..3
    const int warp_n = w & 1;           // 0..1
    const int m0 = blockIdx.y * 128;
    const int n0 = blockIdx.x * 128;
    const int gid = lane >> 2;          // group id 0..7
    const int tig = lane & 3;           // thread-in-group 0..3

    float acc[2][8][4];
    #pragma unroll
    for (int mt = 0; mt < 2; mt++)
        #pragma unroll
        for (int nt = 0; nt < 8; nt++)
            #pragma unroll
            for (int r = 0; r < 4; r++) acc[mt][nt][r] = 0.f;

    // per-thread load slots
    const int arow[4] = { (tid+0)>>3, (tid+256)>>3, (tid+512)>>3, (tid+768)>>3 };
    const int ac4  = tid & 7;
    const int brow[4] = { (tid+0)>>5, (tid+256)>>5, (tid+512)>>5, (tid+768)>>5 };
    const int bc4  = tid & 31;

    float4 pa[4], pb[4];

    #define LOAD_TILE(k0)                                                         \
        { _Pragma("unroll")                                                       \
          for (int i = 0; i < 4; i++) {                                           \
            pa[i] = *(const float4*)&A[(size_t)(m0 + arow[i]) * HID + (k0) + ac4 * 4]; \
            pb[i] = *(const float4*)&B[(size_t)((k0) + brow[i]) * HID + n0 + bc4 * 4]; \
          } }

    #define STORE_TILE(buf)                                                       \
        { _Pragma("unroll")                                                       \
          for (int i = 0; i < 4; i++) {                                           \
            uint4 ua = { f2tf(pa[i].x), f2tf(pa[i].y), f2tf(pa[i].z), f2tf(pa[i].w) }; \
            *(uint4*)&As[(buf) * A_ELEMS + arow[i] * ASTRIDE + ac4 * 4] = ua;     \
            uint4 ub = { f2tf(pb[i].x), f2tf(pb[i].y), f2tf(pb[i].z), f2tf(pb[i].w) }; \
            *(uint4*)&Bs[(buf) * B_ELEMS + brow[i] * BSTRIDE + bc4 * 4] = ub;     \
          } }

    LOAD_TILE(0);
    STORE_TILE(0);
    __syncthreads();

    const int NIT = HID / 32;  // 128
    for (int t = 0; t < NIT; t++) {
        if (t + 1 < NIT) LOAD_TILE((t + 1) * 32);
        const unsigned* Ab = As + (t & 1) * A_ELEMS;
        const unsigned* Bb = Bs + (t & 1) * B_ELEMS;
        #pragma unroll
        for (int ks = 0; ks < 4; ks++) {
            const int kk = ks * 8;
            unsigned af[2][4];
            #pragma unroll
            for (int mt = 0; mt < 2; mt++) {
                int rb = warp_m * 32 + mt * 16 + gid;
                af[mt][0] = Ab[(rb    ) * ASTRIDE + kk + tig    ];
                af[mt][1] = Ab[(rb + 8) * ASTRIDE + kk + tig    ];
                af[mt][2] = Ab[(rb    ) * ASTRIDE + kk + tig + 4];
                af[mt][3] = Ab[(rb + 8) * ASTRIDE + kk + tig + 4];
            }
            #pragma unroll
            for (int nt = 0; nt < 8; nt++) {
                int cb = warp_n * 64 + nt * 8 + gid;
                unsigned bf[2];
                bf[0] = Bb[(kk + tig    ) * BSTRIDE + cb];
                bf[1] = Bb[(kk + tig + 4) * BSTRIDE + cb];
                mma_tf32(acc[0][nt], af[0], bf);
                mma_tf32(acc[1][nt], af[1], bf);
            }
        }
        __syncthreads();
        if (t + 1 < NIT) STORE_TILE((t + 1) & 1);
        __syncthreads();
    }

    // ---- epilogue ----
    if (MODE == 0) {
        #pragma unroll
        for (int mt = 0; mt < 2; mt++)
            #pragma unroll
            for (int half = 0; half < 2; half++) {
                int m = m0 + warp_m * 32 + mt * 16 + gid + half * 8;
                #pragma unroll
                for (int nt = 0; nt < 8; nt++) {
                    int n = n0 + warp_n * 64 + nt * 8 + 2 * tig;
                    float2 v = { acc[mt][nt][half * 2], acc[mt][nt][half * 2 + 1] };
                    *(float2*)&Cparam[(size_t)m * HID + n] = v;
                }
            }
    } else {
        float* dbuf = (dst == 0) ? g_q : (dst == 1) ? g_k : g_v;
        int h = blockIdx.x;  // BN == HDIM
        #pragma unroll
        for (int mt = 0; mt < 2; mt++)
            #pragma unroll
            for (int half = 0; half < 2; half++) {
                int m = m0 + warp_m * 32 + mt * 16 + gid + half * 8;
                int b = m / SEQ, pos = m % SEQ;
                size_t base = ((size_t)(b * NHEADS + h) * SEQ + pos) * HDIM;
                #pragma unroll
                for (int nt = 0; nt < 8; nt++) {
                    int d = warp_n * 64 + nt * 8 + 2 * tig;
                    float2 v = { acc[mt][nt][half * 2], acc[mt][nt][half * 2 + 1] };
                    *(float2*)&dbuf[base + d] = v;
                }
            }
    }
    #undef LOAD_TILE
    #undef STORE_TILE
}

// ---------------- RoPE (q gets 1/sqrt(128) fold) ----------------
__global__ __launch_bounds__(128)
void rope_kernel()
{
    int pos = blockIdx.x;
    int bh  = blockIdx.y;
    int d   = threadIdx.x;
    size_t base = ((size_t)bh * SEQ + pos) * HDIM;
    __shared__ float sq[HDIM], sk[HDIM];
    sq[d] = g_q[base + d];
    sk[d] = g_k[base + d];
    __syncthreads();
    int i = d & 63;
    float inv = expf(-(float)i * (9.210340371976184f / 64.f));
    float ang = (float)pos * inv;
    float c = cosf(ang), s = sinf(ang);
    float rq = (d < 64) ? -sq[d + 64] : sq[d - 64];
    float rk = (d < 64) ? -sk[d + 64] : sk[d - 64];
    const float qscale = 0.08838834764831845f;
    g_q[base + d] = (sq[d] * c + rq * s) * qscale;
    g_k[base + d] = sk[d] * c + rk * s;
}

// ---------------- scores: S = Qr @ Kr^T, causal-skipped 64x64 tiles ----------------
__global__ __launch_bounds__(256)
void scores_kernel()
{
    int kt = blockIdx.x, qt = blockIdx.y, bh = blockIdx.z;
    int q0 = qt * 64, k0 = kt * 64;
    if (k0 > q0 + 63) return;
    const float* Q = g_q + (size_t)bh * SEQ * HDIM;
    const float* K = g_k + (size_t)bh * SEQ * HDIM;
    float*       S = g_s + (size_t)bh * SEQ * SEQ;
    __shared__ float Qs[64][65], Ks[64][65];
    int tid = threadIdx.x;
    int tx = tid & 15, ty = tid >> 4;
    float acc[4][4];
    #pragma unroll
    for (int i = 0; i < 4; i++)
        #pragma unroll
        for (int j = 0; j < 4; j++) acc[i][j] = 0.f;

    for (int c = 0; c < 2; c++) {
        #pragma unroll
        for (int i = 0; i < 4; i++) {
            int slot = tid + i * 256;
            int row = slot >> 4;
            int c4  = slot & 15;
            float4 v = *(const float4*)&Q[(size_t)(q0 + row) * HDIM + c * 64 + c4 * 4];
            Qs[row][c4*4+0]=v.x; Qs[row][c4*4+1]=v.y; Qs[row][c4*4+2]=v.z; Qs[row][c4*4+3]=v.w;
            float4 w = *(const float4*)&K[(size_t)(k0 + row) * HDIM + c * 64 + c4 * 4];
            Ks[row][c4*4+0]=w.x; Ks[row][c4*4+1]=w.y; Ks[row][c4*4+2]=w.z; Ks[row][c4*4+3]=w.w;
        }
        __syncthreads();
        #pragma unroll
        for (int kk = 0; kk < 64; kk++) {
            float rq[4], rk[4];
            #pragma unroll
            for (int i = 0; i < 4; i++) rq[i] = Qs[ty*4+i][kk];
            #pragma unroll
            for (int j = 0; j < 4; j++) rk[j] = Ks[tx*4+j][kk];
            #pragma unroll
            for (int i = 0; i < 4; i++)
                #pragma unroll
                for (int j = 0; j < 4; j++)
                    acc[i][j] = fmaf(rq[i], rk[j], acc[i][j]);
        }
        __syncthreads();
    }
    #pragma unroll
    for (int i = 0; i < 4; i++)
        #pragma unroll
        for (int j = 0; j < 4; j++)
            S[(size_t)(q0 + ty*4 + i) * SEQ + k0 + tx*4 + j] = acc[i][j];
}

// ---------------- landmark grouped softmax ----------------
__global__ __launch_bounds__(64)
void lsoftmax_kernel()
{
    int q  = blockIdx.x;
    int bh = blockIdx.y;
    float* row = g_s + ((size_t)bh * SEQ + q) * SEQ;
    int t  = threadIdx.x;
    int Bq = q >> 6;

    __shared__ float sred[64][17];
    __shared__ float gm[16], gs[16], lm[16];

    float vals[NBLK];
    #pragma unroll
    for (int j = 0; j < NBLK; j++) {
        int k = j * 64 + t;
        vals[j] = (k <= q) ? row[k] : NEGF;
    }

    #pragma unroll
    for (int j = 0; j < NBLK; j++)
        sred[t][j] = (t != 63 && j != Bq) ? vals[j] : NEGF;
    {
        float c15;
        if (t == 63) {
            c15 = NEGF;
            #pragma unroll
            for (int j = 0; j < NBLK; j++) c15 = fmaxf(c15, vals[j]);
        } else c15 = vals[Bq];
        sred[t][15] = c15;
    }
    __syncthreads();
    if (t < 16) {
        float m = NEGF;
        for (int i = 0; i < 64; i++) m = fmaxf(m, sred[i][t]);
        gm[t] = m;
    }
    __syncthreads();

    float e[NBLK];
    #pragma unroll
    for (int j = 0; j < NBLK; j++) {
        int grp = (j == Bq || t == 63) ? 15 : j;
        e[j] = expf(vals[j] - gm[grp]);
    }
    #pragma unroll
    for (int j = 0; j < NBLK; j++)
        sred[t][j] = (t != 63 && j != Bq) ? e[j] : 0.f;
    {
        float s15;
        if (t == 63) {
            s15 = 0.f;
            #pragma unroll
            for (int j = 0; j < NBLK; j++) s15 += e[j];
        } else s15 = e[Bq];
        sred[t][15] = s15;
    }
    __syncthreads();
    if (t < 16) {
        float s = 0.f;
        for (int i = 0; i < 64; i++) s += sred[i][t];
        gs[t] = s;
    }
    __syncthreads();

    float p[NBLK];
    #pragma unroll
    for (int j = 0; j < NBLK; j++) {
        int grp = (j == Bq || t == 63) ? 15 : j;
        p[j] = e[j] / gs[grp];
    }
    if (t == 63) {
        #pragma unroll
        for (int j = 0; j < NBLK; j++) lm[j] = p[j];
    }
    __syncthreads();

    #pragma unroll
    for (int j = 0; j < NBLK; j++) {
        int k = j * 64 + t;
        float w;
        if (j == Bq)        w = p[j];
        else if (t == 63)   w = 0.f;
        else                w = p[j] * lm[j];
        row[k] = w;
    }
}

// ---------------- PV ----------------
__global__ __launch_bounds__(256)
void pv_kernel()
{
    int qt = blockIdx.x, bh = blockIdx.y;
    int q0 = qt * 64;
    const float* P = g_s + (size_t)bh * SEQ * SEQ;
    const float* V = g_v + (size_t)bh * SEQ * HDIM;
    __shared__ float Ps[64][33];
    __shared__ float Vs[32][128];
    int tid = threadIdx.x, tx = tid & 15, ty = tid >> 4;
    float acc[4][8];
    #pragma unroll
    for (int i = 0; i < 4; i++)
        #pragma unroll
        for (int j = 0; j < 8; j++) acc[i][j] = 0.f;

    for (int k0 = 0; k0 < SEQ; k0 += 32) {
        #pragma unroll
        for (int i = 0; i < 2; i++) {
            int slot = tid + i * 256;
            int row = slot >> 3;
            int c4  = slot & 7;
            float4 v = *(const float4*)&P[(size_t)(q0 + row) * SEQ + k0 + c4 * 4];
            Ps[row][c4*4+0]=v.x; Ps[row][c4*4+1]=v.y; Ps[row][c4*4+2]=v.z; Ps[row][c4*4+3]=v.w;
        }
        #pragma unroll
        for (int i = 0; i < 4; i++) {
            int slot = tid + i * 256;
            int row = slot >> 5;
            int c4  = slot & 31;
            *(float4*)&Vs[row][c4*4] = *(const float4*)&V[(size_t)(k0 + row) * HDIM + c4 * 4];
        }
        __syncthreads();
        #pragma unroll
        for (int kk = 0; kk < 32; kk++) {
            float rp[4], rv[8];
            #pragma unroll
            for (int i = 0; i < 4; i++) rp[i] = Ps[ty*4+i][kk];
            *(float4*)&rv[0] = *(const float4*)&Vs[kk][tx*8];
            *(float4*)&rv[4] = *(const float4*)&Vs[kk][tx*8+4];
            #pragma unroll
            for (int i = 0; i < 4; i++)
                #pragma unroll
                for (int j = 0; j < 8; j++)
                    acc[i][j] = fmaf(rp[i], rv[j], acc[i][j]);
        }
        __syncthreads();
    }
    int b = bh >> 5, h = bh & 31;
    #pragma unroll
    for (int i = 0; i < 4; i++) {
        int qq = q0 + ty * 4 + i;
        size_t obase = ((size_t)(b * SEQ + qq)) * HID + h * HDIM + tx * 8;
        *(float4*)&g_o[obase]     = *(float4*)&acc[i][0];
        *(float4*)&g_o[obase + 4] = *(float4*)&acc[i][4];
    }
}

// ---------------- launch ----------------
extern "C" void kernel_launch(void* const* d_in, const int* in_sizes, int n_in,
                              void* d_out, int out_size)
{
    const float* X  = (const float*)d_in[0];
    const float* wq = (const float*)d_in[1];
    const float* wk = (const float*)d_in[2];
    const float* wv = (const float*)d_in[3];
    const float* wo = (const float*)d_in[4];
    float* out = (float*)d_out;

    static int smem_set = 0;
    if (!smem_set) {
        cudaFuncSetAttribute(tgemm<0>, cudaFuncAttributeMaxDynamicSharedMemorySize, TG_SMEM);
        cudaFuncSetAttribute(tgemm<1>, cudaFuncAttributeMaxDynamicSharedMemorySize, TG_SMEM);
        smem_set = 1;
    }

    dim3 gp(HID / 128, MTOT / 128);   // (32, 15)

    tgemm<1><<<gp, 256, TG_SMEM>>>(X, wq, nullptr, 0, 0);
    tgemm<1><<<gp, 256, TG_SMEM>>>(X, wk, nullptr, 0, 1);
    tgemm<1><<<gp, 256, TG_SMEM>>>(X, wv, nullptr, 0, 2);
    rope_kernel<<<dim3(SEQ, BHTOT), 128>>>();
    scores_kernel<<<dim3(NBLK, NBLK, BHTOT), 256>>>();
    lsoftmax_kernel<<<dim3(SEQ, BHTOT), 64>>>();
    pv_kernel<<<dim3(NBLK, BHTOT), 256>>>();
    tgemm<0><<<gp, 256, TG_SMEM>>>(nullptr, wo, out, 1, 0);
}

// round 10
// speedup vs baseline: 2.4042x; 1.0304x over previous
#include <cuda_runtime.h>
#include <math.h>
#include <stdint.h>

#define BATCH   2
#define SEQ     960
#define NHEADS  32
#define HDIM    128
#define HID     4096
#define MTOT    (BATCH*SEQ)     // 1920
#define NBLK    15
#define BHTOT   (BATCH*NHEADS)  // 64
#define NEGF    (-3.4028234663852886e38f)

// ---------------- scratch ----------------
__device__ float g_q[(size_t)BHTOT*SEQ*HDIM];
__device__ float g_k[(size_t)BHTOT*SEQ*HDIM];
__device__ float g_v[(size_t)BHTOT*SEQ*HDIM];
__device__ float g_s[(size_t)BHTOT*SEQ*SEQ];
__device__ float g_o[(size_t)MTOT*HID];        // tf32-rounded by pv epilogue
__device__ float g_wt[4][(size_t)HID*HID];     // tf32-converted weights (no transpose)
__device__ float g_xt[(size_t)MTOT*HID];       // tf32-converted X

// ---------------- helpers ----------------
__device__ __forceinline__ uint32_t smem_u32(const void* p) {
    uint32_t r;
    asm("{ .reg .u64 t; cvta.to.shared.u64 t, %1; cvt.u32.u64 %0, t; }" : "=r"(r) : "l"(p));
    return r;
}
__device__ __forceinline__ unsigned f2tf(float f) {
    unsigned u;
    asm("cvt.rna.tf32.f32 %0, %1;" : "=r"(u) : "f"(f));
    return u;
}
__device__ __forceinline__ void mma_tf32(float* c, const unsigned* a, const unsigned* b) {
    asm volatile(
        "mma.sync.aligned.m16n8k8.row.col.f32.tf32.tf32.f32 "
        "{%0,%1,%2,%3}, {%4,%5,%6,%7}, {%8,%9}, {%0,%1,%2,%3};"
        : "+f"(c[0]), "+f"(c[1]), "+f"(c[2]), "+f"(c[3])
        : "r"(a[0]), "r"(a[1]), "r"(a[2]), "r"(a[3]), "r"(b[0]), "r"(b[1]));
}
__device__ __forceinline__ void cp16(uint32_t s, const void* g) {
    asm volatile("cp.async.cg.shared.global [%0], [%1], 16;" :: "r"(s), "l"(g) : "memory");
}
#define CP_COMMIT() asm volatile("cp.async.commit_group;" ::: "memory")
#define CP_WAIT1()  asm volatile("cp.async.wait_group 1;" ::: "memory")
#define CP_WAIT0()  asm volatile("cp.async.wait_group 0;" ::: "memory")

// ---------------- elementwise f32 -> tf32 convert ----------------
__global__ __launch_bounds__(256)
void conv_tf32(const float* __restrict__ src, float* __restrict__ dst, int n4)
{
    int i = blockIdx.x * 256 + threadIdx.x;
    if (i < n4) {
        float4 v = *(const float4*)&src[(size_t)i * 4];
        uint4 u = { f2tf(v.x), f2tf(v.y), f2tf(v.z), f2tf(v.w) };
        *(uint4*)&dst[(size_t)i * 4] = u;
    }
}

// ---------------- tf32 GEMM: 128x128 tile, BK=32, 3-stage cp.async ----------------
// Inputs already tf32-rounded. A K-major [M][K], B row-major [K][N].
// MODE 0: C -> Cparam row-major (A = g_o when asrc)
// MODE 1: headed store -> g_q/g_k/g_v ; h = blockIdx.x
#define ASTRIDE 36
#define BSTRIDE 136
#define A_ELEMS (128*ASTRIDE)          // 4608 floats
#define B_ELEMS (32*BSTRIDE)           // 4352 floats
#define STG_ELEMS (A_ELEMS + B_ELEMS)  // 8960 floats
#define NSTAGE 3
#define TG_SMEM (NSTAGE*STG_ELEMS*4)   // 107,520 B

template<int MODE>
__global__ __launch_bounds__(256, 1)
void tgemm(const float* __restrict__ Aparam, const float* __restrict__ B,
           float* __restrict__ Cparam, int asrc, int dst)
{
    const float* A = asrc ? (const float*)g_o : Aparam;
    extern __shared__ unsigned sm[];
    const uint32_t smbase = smem_u32(sm);

    const int tid  = threadIdx.x;
    const int lane = tid & 31;
    const int w    = tid >> 5;
    const int warp_m = w >> 1;          // 0..3
    const int warp_n = w & 1;           // 0..1
    const int m0 = blockIdx.y * 128;
    const int n0 = blockIdx.x * 128;
    const int gid = lane >> 2;
    const int tig = lane & 3;

    float acc[2][8][4];
    #pragma unroll
    for (int mt = 0; mt < 2; mt++)
        #pragma unroll
        for (int nt = 0; nt < 8; nt++)
            #pragma unroll
            for (int r = 0; r < 4; r++) acc[mt][nt][r] = 0.f;

    // per-thread cp.async slots: 4 chunks of 16B each for A and B
    const int arow[4] = { (tid+0)>>3, (tid+256)>>3, (tid+512)>>3, (tid+768)>>3 };
    const int ac16 = tid & 7;
    const int brow[4] = { (tid+0)>>5, (tid+256)>>5, (tid+512)>>5, (tid+768)>>5 };
    const int bc16 = tid & 31;
    uint32_t aoff[4], boff[4];
    #pragma unroll
    for (int i = 0; i < 4; i++) {
        aoff[i] = (uint32_t)(arow[i] * ASTRIDE + ac16 * 4) * 4u;
        boff[i] = (uint32_t)(A_ELEMS + brow[i] * BSTRIDE + bc16 * 4) * 4u;
    }

    #define ISSUE(st, k0)                                                           \
        { uint32_t sb = smbase + (uint32_t)(st) * (STG_ELEMS * 4);                  \
          _Pragma("unroll")                                                         \
          for (int i = 0; i < 4; i++) {                                             \
            cp16(sb + aoff[i], &A[(size_t)(m0 + arow[i]) * HID + (k0) + ac16 * 4]); \
            cp16(sb + boff[i], &B[(size_t)((k0) + brow[i]) * HID + n0 + bc16 * 4]); \
          }                                                                         \
          CP_COMMIT(); }

    const int NIT = HID / 32;   // 128
    ISSUE(0, 0);
    ISSUE(1, 32);

    int st = 0;
    for (int t = 0; t < NIT; t++) {
        if (t + 2 < NIT) CP_WAIT1(); else CP_WAIT0();
        __syncthreads();
        if (t + 2 < NIT) {
            int st2 = st + 2; if (st2 >= NSTAGE) st2 -= NSTAGE;
            ISSUE(st2, (t + 2) * 32);
        }
        const unsigned* Ab = sm + st * STG_ELEMS;
        const unsigned* Bb = Ab + A_ELEMS;
        #pragma unroll
        for (int ks = 0; ks < 4; ks++) {
            const int kk = ks * 8;
            unsigned af[2][4];
            #pragma unroll
            for (int mt = 0; mt < 2; mt++) {
                int rb = warp_m * 32 + mt * 16 + gid;
                af[mt][0] = Ab[(rb    ) * ASTRIDE + kk + tig    ];
                af[mt][1] = Ab[(rb + 8) * ASTRIDE + kk + tig    ];
                af[mt][2] = Ab[(rb    ) * ASTRIDE + kk + tig + 4];
                af[mt][3] = Ab[(rb + 8) * ASTRIDE + kk + tig + 4];
            }
            #pragma unroll
            for (int nt = 0; nt < 8; nt++) {
                int cb = warp_n * 64 + nt * 8 + gid;
                unsigned bf[2];
                bf[0] = Bb[(kk + tig    ) * BSTRIDE + cb];
                bf[1] = Bb[(kk + tig + 4) * BSTRIDE + cb];
                mma_tf32(acc[0][nt], af[0], bf);
                mma_tf32(acc[1][nt], af[1], bf);
            }
        }
        __syncthreads();
        if (++st == NSTAGE) st = 0;
    }

    // ---- epilogue ----
    if (MODE == 0) {
        #pragma unroll
        for (int mt = 0; mt < 2; mt++)
            #pragma unroll
            for (int half = 0; half < 2; half++) {
                int m = m0 + warp_m * 32 + mt * 16 + gid + half * 8;
                #pragma unroll
                for (int nt = 0; nt < 8; nt++) {
                    int n = n0 + warp_n * 64 + nt * 8 + 2 * tig;
                    float2 v = { acc[mt][nt][half * 2], acc[mt][nt][half * 2 + 1] };
                    *(float2*)&Cparam[(size_t)m * HID + n] = v;
                }
            }
    } else {
        float* dbuf = (dst == 0) ? g_q : (dst == 1) ? g_k : g_v;
        int h = blockIdx.x;
        #pragma unroll
        for (int mt = 0; mt < 2; mt++)
            #pragma unroll
            for (int half = 0; half < 2; half++) {
                int m = m0 + warp_m * 32 + mt * 16 + gid + half * 8;
                int b = m / SEQ, pos = m % SEQ;
                size_t base = ((size_t)(b * NHEADS + h) * SEQ + pos) * HDIM;
                #pragma unroll
                for (int nt = 0; nt < 8; nt++) {
                    int d = warp_n * 64 + nt * 8 + 2 * tig;
                    float2 v = { acc[mt][nt][half * 2], acc[mt][nt][half * 2 + 1] };
                    *(float2*)&dbuf[base + d] = v;
                }
            }
    }
    #undef ISSUE
}

// ---------------- RoPE (q gets 1/sqrt(128) fold) ----------------
__global__ __launch_bounds__(128)
void rope_kernel()
{
    int pos = blockIdx.x;
    int bh  = blockIdx.y;
    int d   = threadIdx.x;
    size_t base = ((size_t)bh * SEQ + pos) * HDIM;
    __shared__ float sq[HDIM], sk[HDIM];
    sq[d] = g_q[base + d];
    sk[d] = g_k[base + d];
    __syncthreads();
    int i = d & 63;
    float inv = expf(-(float)i * (9.210340371976184f / 64.f));
    float ang = (float)pos * inv;
    float c = cosf(ang), s = sinf(ang);
    float rq = (d < 64) ? -sq[d + 64] : sq[d - 64];
    float rk = (d < 64) ? -sk[d + 64] : sk[d - 64];
    const float qscale = 0.08838834764831845f;
    g_q[base + d] = (sq[d] * c + rq * s) * qscale;
    g_k[base + d] = sk[d] * c + rk * s;
}

// ---------------- scores: S = Qr @ Kr^T, causal-skipped 64x64 tiles ----------------
__global__ __launch_bounds__(256)
void scores_kernel()
{
    int kt = blockIdx.x, qt = blockIdx.y, bh = blockIdx.z;
    int q0 = qt * 64, k0 = kt * 64;
    if (k0 > q0 + 63) return;
    const float* Q = g_q + (size_t)bh * SEQ * HDIM;
    const float* K = g_k + (size_t)bh * SEQ * HDIM;
    float*       S = g_s + (size_t)bh * SEQ * SEQ;
    __shared__ float Qs[64][65], Ks[64][65];
    int tid = threadIdx.x;
    int tx = tid & 15, ty = tid >> 4;
    float acc[4][4];
    #pragma unroll
    for (int i = 0; i < 4; i++)
        #pragma unroll
        for (int j = 0; j < 4; j++) acc[i][j] = 0.f;

    for (int c = 0; c < 2; c++) {
        #pragma unroll
        for (int i = 0; i < 4; i++) {
            int slot = tid + i * 256;
            int row = slot >> 4;
            int c4  = slot & 15;
            float4 v = *(const float4*)&Q[(size_t)(q0 + row) * HDIM + c * 64 + c4 * 4];
            Qs[row][c4*4+0]=v.x; Qs[row][c4*4+1]=v.y; Qs[row][c4*4+2]=v.z; Qs[row][c4*4+3]=v.w;
            float4 w = *(const float4*)&K[(size_t)(k0 + row) * HDIM + c * 64 + c4 * 4];
            Ks[row][c4*4+0]=w.x; Ks[row][c4*4+1]=w.y; Ks[row][c4*4+2]=w.z; Ks[row][c4*4+3]=w.w;
        }
        __syncthreads();
        #pragma unroll
        for (int kk = 0; kk < 64; kk++) {
            float rq[4], rk[4];
            #pragma unroll
            for (int i = 0; i < 4; i++) rq[i] = Qs[ty*4+i][kk];
            #pragma unroll
            for (int j = 0; j < 4; j++) rk[j] = Ks[tx*4+j][kk];
            #pragma unroll
            for (int i = 0; i < 4; i++)
                #pragma unroll
                for (int j = 0; j < 4; j++)
                    acc[i][j] = fmaf(rq[i], rk[j], acc[i][j]);
        }
        __syncthreads();
    }
    #pragma unroll
    for (int i = 0; i < 4; i++)
        #pragma unroll
        for (int j = 0; j < 4; j++)
            S[(size_t)(q0 + ty*4 + i) * SEQ + k0 + tx*4 + j] = acc[i][j];
}

// ---------------- landmark grouped softmax ----------------
__global__ __launch_bounds__(64)
void lsoftmax_kernel()
{
    int q  = blockIdx.x;
    int bh = blockIdx.y;
    float* row = g_s + ((size_t)bh * SEQ + q) * SEQ;
    int t  = threadIdx.x;
    int Bq = q >> 6;

    __shared__ float sred[64][17];
    __shared__ float gm[16], gs[16], lm[16];

    float vals[NBLK];
    #pragma unroll
    for (int j = 0; j < NBLK; j++) {
        int k = j * 64 + t;
        vals[j] = (k <= q) ? row[k] : NEGF;
    }

    #pragma unroll
    for (int j = 0; j < NBLK; j++)
        sred[t][j] = (t != 63 && j != Bq) ? vals[j] : NEGF;
    {
        float c15;
        if (t == 63) {
            c15 = NEGF;
            #pragma unroll
            for (int j = 0; j < NBLK; j++) c15 = fmaxf(c15, vals[j]);
        } else c15 = vals[Bq];
        sred[t][15] = c15;
    }
    __syncthreads();
    if (t < 16) {
        float m = NEGF;
        for (int i = 0; i < 64; i++) m = fmaxf(m, sred[i][t]);
        gm[t] = m;
    }
    __syncthreads();

    float e[NBLK];
    #pragma unroll
    for (int j = 0; j < NBLK; j++) {
        int grp = (j == Bq || t == 63) ? 15 : j;
        e[j] = expf(vals[j] - gm[grp]);
    }
    #pragma unroll
    for (int j = 0; j < NBLK; j++)
        sred[t][j] = (t != 63 && j != Bq) ? e[j] : 0.f;
    {
        float s15;
        if (t == 63) {
            s15 = 0.f;
            #pragma unroll
            for (int j = 0; j < NBLK; j++) s15 += e[j];
        } else s15 = e[Bq];
        sred[t][15] = s15;
    }
    __syncthreads();
    if (t < 16) {
        float s = 0.f;
        for (int i = 0; i < 64; i++) s += sred[i][t];
        gs[t] = s;
    }
    __syncthreads();

    float p[NBLK];
    #pragma unroll
    for (int j = 0; j < NBLK; j++) {
        int grp = (j == Bq || t == 63) ? 15 : j;
        p[j] = e[j] / gs[grp];
    }
    if (t == 63) {
        #pragma unroll
        for (int j = 0; j < NBLK; j++) lm[j] = p[j];
    }
    __syncthreads();

    #pragma unroll
    for (int j = 0; j < NBLK; j++) {
        int k = j * 64 + t;
        float w;
        if (j == Bq)        w = p[j];
        else if (t == 63)   w = 0.f;
        else                w = p[j] * lm[j];
        row[k] = w;
    }
}

// ---------------- PV (stores tf32-rounded output for the Wo GEMM) ----------------
__global__ __launch_bounds__(256)
void pv_kernel()
{
    int qt = blockIdx.x, bh = blockIdx.y;
    int q0 = qt * 64;
    const float* P = g_s + (size_t)bh * SEQ * SEQ;
    const float* V = g_v + (size_t)bh * SEQ * HDIM;
    __shared__ float Ps[64][33];
    __shared__ float Vs[32][128];
    int tid = threadIdx.x, tx = tid & 15, ty = tid >> 4;
    float acc[4][8];
    #pragma unroll
    for (int i = 0; i < 4; i++)
        #pragma unroll
        for (int j = 0; j < 8; j++) acc[i][j] = 0.f;

    for (int k0 = 0; k0 < SEQ; k0 += 32) {
        #pragma unroll
        for (int i = 0; i < 2; i++) {
            int slot = tid + i * 256;
            int row = slot >> 3;
            int c4  = slot & 7;
            float4 v = *(const float4*)&P[(size_t)(q0 + row) * SEQ + k0 + c4 * 4];
            Ps[row][c4*4+0]=v.x; Ps[row][c4*4+1]=v.y; Ps[row][c4*4+2]=v.z; Ps[row][c4*4+3]=v.w;
        }
        #pragma unroll
        for (int i = 0; i < 4; i++) {
            int slot = tid + i * 256;
            int row = slot >> 5;
            int c4  = slot & 31;
            *(float4*)&Vs[row][c4*4] = *(const float4*)&V[(size_t)(k0 + row) * HDIM + c4 * 4];
        }
        __syncthreads();
        #pragma unroll
        for (int kk = 0; kk < 32; kk++) {
            float rp[4], rv[8];
            #pragma unroll
            for (int i = 0; i < 4; i++) rp[i] = Ps[ty*4+i][kk];
            *(float4*)&rv[0] = *(const float4*)&Vs[kk][tx*8];
            *(float4*)&rv[4] = *(const float4*)&Vs[kk][tx*8+4];
            #pragma unroll
            for (int i = 0; i < 4; i++)
                #pragma unroll
                for (int j = 0; j < 8; j++)
                    acc[i][j] = fmaf(rp[i], rv[j], acc[i][j]);
        }
        __syncthreads();
    }
    int b = bh >> 5, h = bh & 31;
    #pragma unroll
    for (int i = 0; i < 4; i++) {
        int qq = q0 + ty * 4 + i;
        size_t obase = ((size_t)(b * SEQ + qq)) * HID + h * HDIM + tx * 8;
        uint4 lo = { f2tf(acc[i][0]), f2tf(acc[i][1]), f2tf(acc[i][2]), f2tf(acc[i][3]) };
        uint4 hi = { f2tf(acc[i][4]), f2tf(acc[i][5]), f2tf(acc[i][6]), f2tf(acc[i][7]) };
        *(uint4*)&g_o[obase]     = lo;
        *(uint4*)&g_o[obase + 4] = hi;
    }
}

// ---------------- launch ----------------
extern "C" void kernel_launch(void* const* d_in, const int* in_sizes, int n_in,
                              void* d_out, int out_size)
{
    const float* X  = (const float*)d_in[0];
    const float* wq = (const float*)d_in[1];
    const float* wk = (const float*)d_in[2];
    const float* wv = (const float*)d_in[3];
    const float* wo = (const float*)d_in[4];
    float* out = (float*)d_out;

    static int init_done = 0;
    if (!init_done) {
        cudaFuncSetAttribute(tgemm<0>, cudaFuncAttributeMaxDynamicSharedMemorySize, TG_SMEM);
        cudaFuncSetAttribute(tgemm<1>, cudaFuncAttributeMaxDynamicSharedMemorySize, TG_SMEM);
        init_done = 1;
    }

    float* wtBase; cudaGetSymbolAddress((void**)&wtBase, g_wt);
    float* xtBase; cudaGetSymbolAddress((void**)&xtBase, g_xt);
    const float* wT[4] = { wtBase, wtBase + (size_t)HID*HID,
                           wtBase + 2*(size_t)HID*HID, wtBase + 3*(size_t)HID*HID };

    const int W4 = HID * HID / 4;          // 4,194,304
    const int X4 = MTOT * HID / 4;         // 1,966,080
    conv_tf32<<<(X4 + 255) / 256, 256>>>(X,  xtBase, X4);
    conv_tf32<<<(W4 + 255) / 256, 256>>>(wq, (float*)wT[0], W4);
    conv_tf32<<<(W4 + 255) / 256, 256>>>(wk, (float*)wT[1], W4);
    conv_tf32<<<(W4 + 255) / 256, 256>>>(wv, (float*)wT[2], W4);
    conv_tf32<<<(W4 + 255) / 256, 256>>>(wo, (float*)wT[3], W4);

    dim3 gp(HID / 128, MTOT / 128);   // (32, 15)
    tgemm<1><<<gp, 256, TG_SMEM>>>(xtBase, wT[0], nullptr, 0, 0);
    tgemm<1><<<gp, 256, TG_SMEM>>>(xtBase, wT[1], nullptr, 0, 1);
    tgemm<1><<<gp, 256, TG_SMEM>>>(xtBase, wT[2], nullptr, 0, 2);
    rope_kernel<<<dim3(SEQ, BHTOT), 128>>>();
    scores_kernel<<<dim3(NBLK, NBLK, BHTOT), 256>>>();
    lsoftmax_kernel<<<dim3(SEQ, BHTOT), 64>>>();
    pv_kernel<<<dim3(NBLK, BHTOT), 256>>>();
    tgemm<0><<<gp, 256, TG_SMEM>>>(nullptr, wT[3], out, 1, 0);
}

// round 11
// speedup vs baseline: 2.6915x; 1.1195x over previous
#include <cuda_runtime.h>
#include <math.h>
#include <stdint.h>

#define BATCH   2
#define SEQ     960
#define NHEADS  32
#define HDIM    128
#define HID     4096
#define MTOT    (BATCH*SEQ)     // 1920
#define NBLK    15
#define BHTOT   (BATCH*NHEADS)  // 64
#define NEGF    (-3.4028234663852886e38f)

// ---------------- scratch ----------------
__device__ float g_q[(size_t)BHTOT*SEQ*HDIM];
__device__ float g_k[(size_t)BHTOT*SEQ*HDIM];
__device__ float g_v[(size_t)BHTOT*SEQ*HDIM];
__device__ float g_s[(size_t)BHTOT*SEQ*SEQ];
__device__ float g_o[(size_t)MTOT*HID];        // pv output (tf32-rounded)
__device__ float g_wt[4][(size_t)HID*HID];     // fragment-packed tf32 weights
__device__ float g_xt[(size_t)MTOT*HID];       // fragment-packed tf32 X
__device__ float g_ot[(size_t)MTOT*HID];       // fragment-packed tf32 g_o

// ---------------- helpers ----------------
__device__ __forceinline__ uint32_t smem_u32(const void* p) {
    uint32_t r;
    asm("{ .reg .u64 t; cvta.to.shared.u64 t, %1; cvt.u32.u64 %0, t; }" : "=r"(r) : "l"(p));
    return r;
}
__device__ __forceinline__ unsigned f2tf(float f) {
    unsigned u;
    asm("cvt.rna.tf32.f32 %0, %1;" : "=r"(u) : "f"(f));
    return u;
}
__device__ __forceinline__ void mma_tf32(float* c, const unsigned* a, const unsigned* b) {
    asm volatile(
        "mma.sync.aligned.m16n8k8.row.col.f32.tf32.tf32.f32 "
        "{%0,%1,%2,%3}, {%4,%5,%6,%7}, {%8,%9}, {%0,%1,%2,%3};"
        : "+f"(c[0]), "+f"(c[1]), "+f"(c[2]), "+f"(c[3])
        : "r"(a[0]), "r"(a[1]), "r"(a[2]), "r"(a[3]), "r"(b[0]), "r"(b[1]));
}
__device__ __forceinline__ void cp16(uint32_t s, const void* g) {
    asm volatile("cp.async.cg.shared.global [%0], [%1], 16;" :: "r"(s), "l"(g) : "memory");
}
#define CP_COMMIT() asm volatile("cp.async.commit_group;" ::: "memory")
#define CP_WAIT2()  asm volatile("cp.async.wait_group 2;" ::: "memory")
#define CP_WAIT1()  asm volatile("cp.async.wait_group 1;" ::: "memory")
#define CP_WAIT0()  asm volatile("cp.async.wait_group 0;" ::: "memory")

// ---------------- pack A: [M][K] f32 -> fragment-packed tf32 tiles ----------------
// tile (mb, kb): base = (mb*(K/32)+kb)*4096 floats
// within: uint4 index c = (rb*4+ks)*32+lane ; lane = gid*4+tig
//   e0 = A[mb*128+rb*16+gid  ][kb*32+ks*8+tig  ]
//   e1 = A[...+8             ][...              ]
//   e2 = A[...               ][...+4            ]
//   e3 = A[...+8             ][...+4            ]
__global__ __launch_bounds__(256)
void pack_a(const float* __restrict__ src, float* __restrict__ dst)
{
    const int kb = blockIdx.x;             // K/32
    const int mb = blockIdx.y;             // M/128
    const int tid = threadIdx.x;
    float* tb = dst + ((size_t)mb * (HID / 32) + kb) * 4096;
    #pragma unroll
    for (int it = 0; it < 4; it++) {
        int c = tid + it * 256;
        int lane = c & 31, r = c >> 5;
        int ks = r & 3, rb = r >> 2;
        int gid = lane >> 2, tig = lane & 3;
        size_t m = mb * 128 + rb * 16 + gid;
        size_t k = kb * 32 + ks * 8 + tig;
        uint4 u;
        u.x = f2tf(src[m * HID + k]);
        u.y = f2tf(src[(m + 8) * HID + k]);
        u.z = f2tf(src[m * HID + k + 4]);
        u.w = f2tf(src[(m + 8) * HID + k + 4]);
        *(uint4*)&tb[(size_t)c * 4] = u;
    }
}

// ---------------- pack B: W[K][N] f32 -> fragment-packed tf32 tiles ----------------
// tile (kb, nb): base = (kb*(N/128)+nb)*4096 floats
// uint4 index c = (ngp*4+ks)*32+lane
//   e0 = W[kb*32+ks*8+tig  ][nb*128+ngp*16+gid  ]
//   e1 = W[...+4           ][...                ]
//   e2 = W[...             ][...+8              ]
//   e3 = W[...+4           ][...+8              ]
__global__ __launch_bounds__(256)
void pack_b(const float* __restrict__ w0, const float* __restrict__ w1,
            const float* __restrict__ w2, const float* __restrict__ w3)
{
    const float* src = (blockIdx.z == 0) ? w0 : (blockIdx.z == 1) ? w1
                     : (blockIdx.z == 2) ? w2 : w3;
    float* dst = g_wt[blockIdx.z];
    const int nb = blockIdx.x;             // N/128
    const int kb = blockIdx.y;             // K/32
    const int tid = threadIdx.x;
    float* tb = dst + ((size_t)kb * (HID / 128) + nb) * 4096;
    #pragma unroll
    for (int it = 0; it < 4; it++) {
        int c = tid + it * 256;
        int lane = c & 31, r = c >> 5;
        int ks = r & 3, ngp = r >> 2;
        int gid = lane >> 2, tig = lane & 3;
        size_t k = kb * 32 + ks * 8 + tig;
        size_t n = nb * 128 + ngp * 16 + gid;
        uint4 u;
        u.x = f2tf(src[k * HID + n]);
        u.y = f2tf(src[(k + 4) * HID + n]);
        u.z = f2tf(src[k * HID + n + 8]);
        u.w = f2tf(src[(k + 4) * HID + n + 8]);
        *(uint4*)&tb[(size_t)c * 4] = u;
    }
}

// ---------------- tf32 GEMM on packed operands: 128x128 tile, BK=32 ----------------
// MODE 0: C -> Cparam row-major ; MODE 1: headed store -> g_q/g_k/g_v, h = blockIdx.x
#define STAGE_FLTS 8192                   // A 4096 + B 4096 floats
#define STAGE_B    (STAGE_FLTS*4)
#define NSTAGE     4
#define TG_SMEM    (NSTAGE*STAGE_B)       // 131072

template<int MODE>
__global__ __launch_bounds__(256, 1)
void tgemm(const float* __restrict__ Apk, const float* __restrict__ Bpk,
           float* __restrict__ Cparam, int dst)
{
    extern __shared__ unsigned sm[];
    const uint32_t smbase = smem_u32(sm);

    const int tid  = threadIdx.x;
    const int lane = tid & 31;
    const int w    = tid >> 5;
    const int warp_m = w >> 1;          // 0..3
    const int warp_n = w & 1;           // 0..1
    const int nb = blockIdx.x;
    const int mb = blockIdx.y;
    const int gid = lane >> 2;
    const int tig = lane & 3;

    float acc[2][8][4];
    #pragma unroll
    for (int mt = 0; mt < 2; mt++)
        #pragma unroll
        for (int nt = 0; nt < 8; nt++)
            #pragma unroll
            for (int r = 0; r < 4; r++) acc[mt][nt][r] = 0.f;

    #define ISSUE(st, kb)                                                        \
        { uint32_t sb = smbase + (uint32_t)(st) * STAGE_B;                       \
          const float* ga = Apk + ((size_t)mb * (HID/32) + (kb)) * 4096;         \
          const float* gb = Bpk + ((size_t)(kb) * (HID/128) + nb) * 4096;        \
          _Pragma("unroll")                                                      \
          for (int it = 0; it < 4; it++) {                                       \
            int c = tid + it * 256;                                              \
            cp16(sb + c * 16,         ga + (size_t)c * 4);                       \
            cp16(sb + 16384 + c * 16, gb + (size_t)c * 4);                       \
          }                                                                      \
          CP_COMMIT(); }

    const int NIT = HID / 32;   // 128
    ISSUE(0, 0); ISSUE(1, 1); ISSUE(2, 2);

    for (int t = 0; t < NIT; t++) {
        if (t < NIT - 2)      CP_WAIT2();
        else if (t == NIT - 2) CP_WAIT1();
        else                  CP_WAIT0();
        __syncthreads();
        if (t + 3 < NIT) ISSUE((t + 3) & 3, t + 3);

        const uint4* A4 = (const uint4*)(sm + (size_t)(t & 3) * STAGE_FLTS);
        const uint4* B4 = A4 + 1024;      // B starts 16KB in (1024 uint4)
        #pragma unroll
        for (int ks = 0; ks < 4; ks++) {
            uint4 afv[2], bfv[4];
            #pragma unroll
            for (int mt = 0; mt < 2; mt++)
                afv[mt] = A4[((warp_m * 2 + mt) * 4 + ks) * 32 + lane];
            #pragma unroll
            for (int g = 0; g < 4; g++)
                bfv[g] = B4[((warp_n * 4 + g) * 4 + ks) * 32 + lane];
            #pragma unroll
            for (int g = 0; g < 4; g++) {
                unsigned b0[2] = { bfv[g].x, bfv[g].y };
                unsigned b1[2] = { bfv[g].z, bfv[g].w };
                #pragma unroll
                for (int mt = 0; mt < 2; mt++) {
                    mma_tf32(acc[mt][2 * g],     (const unsigned*)&afv[mt], b0);
                    mma_tf32(acc[mt][2 * g + 1], (const unsigned*)&afv[mt], b1);
                }
            }
        }
    }

    // ---- epilogue (unchanged mapping) ----
    const int m0 = mb * 128, n0 = nb * 128;
    if (MODE == 0) {
        #pragma unroll
        for (int mt = 0; mt < 2; mt++)
            #pragma unroll
            for (int half = 0; half < 2; half++) {
                int m = m0 + warp_m * 32 + mt * 16 + gid + half * 8;
                #pragma unroll
                for (int nt = 0; nt < 8; nt++) {
                    int n = n0 + warp_n * 64 + nt * 8 + 2 * tig;
                    float2 v = { acc[mt][nt][half * 2], acc[mt][nt][half * 2 + 1] };
                    *(float2*)&Cparam[(size_t)m * HID + n] = v;
                }
            }
    } else {
        float* dbuf = (dst == 0) ? g_q : (dst == 1) ? g_k : g_v;
        int h = nb;
        #pragma unroll
        for (int mt = 0; mt < 2; mt++)
            #pragma unroll
            for (int half = 0; half < 2; half++) {
                int m = m0 + warp_m * 32 + mt * 16 + gid + half * 8;
                int b = m / SEQ, pos = m % SEQ;
                size_t base = ((size_t)(b * NHEADS + h) * SEQ + pos) * HDIM;
                #pragma unroll
                for (int nt = 0; nt < 8; nt++) {
                    int d = warp_n * 64 + nt * 8 + 2 * tig;
                    float2 v = { acc[mt][nt][half * 2], acc[mt][nt][half * 2 + 1] };
                    *(float2*)&dbuf[base + d] = v;
                }
            }
    }
    #undef ISSUE
}

// ---------------- RoPE (q gets 1/sqrt(128) fold) ----------------
__global__ __launch_bounds__(128)
void rope_kernel()
{
    int pos = blockIdx.x;
    int bh  = blockIdx.y;
    int d   = threadIdx.x;
    size_t base = ((size_t)bh * SEQ + pos) * HDIM;
    __shared__ float sq[HDIM], sk[HDIM];
    sq[d] = g_q[base + d];
    sk[d] = g_k[base + d];
    __syncthreads();
    int i = d & 63;
    float inv = expf(-(float)i * (9.210340371976184f / 64.f));
    float ang = (float)pos * inv;
    float c = cosf(ang), s = sinf(ang);
    float rq = (d < 64) ? -sq[d + 64] : sq[d - 64];
    float rk = (d < 64) ? -sk[d + 64] : sk[d - 64];
    const float qscale = 0.08838834764831845f;
    g_q[base + d] = (sq[d] * c + rq * s) * qscale;
    g_k[base + d] = sk[d] * c + rk * s;
}

// ---------------- scores: S = Qr @ Kr^T, causal-skipped 64x64 tiles ----------------
__global__ __launch_bounds__(256)
void scores_kernel()
{
    int kt = blockIdx.x, qt = blockIdx.y, bh = blockIdx.z;
    int q0 = qt * 64, k0 = kt * 64;
    if (k0 > q0 + 63) return;
    const float* Q = g_q + (size_t)bh * SEQ * HDIM;
    const float* K = g_k + (size_t)bh * SEQ * HDIM;
    float*       S = g_s + (size_t)bh * SEQ * SEQ;
    __shared__ float Qs[64][65], Ks[64][65];
    int tid = threadIdx.x;
    int tx = tid & 15, ty = tid >> 4;
    float acc[4][4];
    #pragma unroll
    for (int i = 0; i < 4; i++)
        #pragma unroll
        for (int j = 0; j < 4; j++) acc[i][j] = 0.f;

    for (int c = 0; c < 2; c++) {
        #pragma unroll
        for (int i = 0; i < 4; i++) {
            int slot = tid + i * 256;
            int row = slot >> 4;
            int c4  = slot & 15;
            float4 v = *(const float4*)&Q[(size_t)(q0 + row) * HDIM + c * 64 + c4 * 4];
            Qs[row][c4*4+0]=v.x; Qs[row][c4*4+1]=v.y; Qs[row][c4*4+2]=v.z; Qs[row][c4*4+3]=v.w;
            float4 w = *(const float4*)&K[(size_t)(k0 + row) * HDIM + c * 64 + c4 * 4];
            Ks[row][c4*4+0]=w.x; Ks[row][c4*4+1]=w.y; Ks[row][c4*4+2]=w.z; Ks[row][c4*4+3]=w.w;
        }
        __syncthreads();
        #pragma unroll
        for (int kk = 0; kk < 64; kk++) {
            float rq[4], rk[4];
            #pragma unroll
            for (int i = 0; i < 4; i++) rq[i] = Qs[ty*4+i][kk];
            #pragma unroll
            for (int j = 0; j < 4; j++) rk[j] = Ks[tx*4+j][kk];
            #pragma unroll
            for (int i = 0; i < 4; i++)
                #pragma unroll
                for (int j = 0; j < 4; j++)
                    acc[i][j] = fmaf(rq[i], rk[j], acc[i][j]);
        }
        __syncthreads();
    }
    #pragma unroll
    for (int i = 0; i < 4; i++)
        #pragma unroll
        for (int j = 0; j < 4; j++)
            S[(size_t)(q0 + ty*4 + i) * SEQ + k0 + tx*4 + j] = acc[i][j];
}

// ---------------- landmark grouped softmax ----------------
__global__ __launch_bounds__(64)
void lsoftmax_kernel()
{
    int q  = blockIdx.x;
    int bh = blockIdx.y;
    float* row = g_s + ((size_t)bh * SEQ + q) * SEQ;
    int t  = threadIdx.x;
    int Bq = q >> 6;

    __shared__ float sred[64][17];
    __shared__ float gm[16], gs[16], lm[16];

    float vals[NBLK];
    #pragma unroll
    for (int j = 0; j < NBLK; j++) {
        int k = j * 64 + t;
        vals[j] = (k <= q) ? row[k] : NEGF;
    }

    #pragma unroll
    for (int j = 0; j < NBLK; j++)
        sred[t][j] = (t != 63 && j != Bq) ? vals[j] : NEGF;
    {
        float c15;
        if (t == 63) {
            c15 = NEGF;
            #pragma unroll
            for (int j = 0; j < NBLK; j++) c15 = fmaxf(c15, vals[j]);
        } else c15 = vals[Bq];
        sred[t][15] = c15;
    }
    __syncthreads();
    if (t < 16) {
        float m = NEGF;
        for (int i = 0; i < 64; i++) m = fmaxf(m, sred[i][t]);
        gm[t] = m;
    }
    __syncthreads();

    float e[NBLK];
    #pragma unroll
    for (int j = 0; j < NBLK; j++) {
        int grp = (j == Bq || t == 63) ? 15 : j;
        e[j] = expf(vals[j] - gm[grp]);
    }
    #pragma unroll
    for (int j = 0; j < NBLK; j++)
        sred[t][j] = (t != 63 && j != Bq) ? e[j] : 0.f;
    {
        float s15;
        if (t == 63) {
            s15 = 0.f;
            #pragma unroll
            for (int j = 0; j < NBLK; j++) s15 += e[j];
        } else s15 = e[Bq];
        sred[t][15] = s15;
    }
    __syncthreads();
    if (t < 16) {
        float s = 0.f;
        for (int i = 0; i < 64; i++) s += sred[i][t];
        gs[t] = s;
    }
    __syncthreads();

    float p[NBLK];
    #pragma unroll
    for (int j = 0; j < NBLK; j++) {
        int grp = (j == Bq || t == 63) ? 15 : j;
        p[j] = e[j] / gs[grp];
    }
    if (t == 63) {
        #pragma unroll
        for (int j = 0; j < NBLK; j++) lm[j] = p[j];
    }
    __syncthreads();

    #pragma unroll
    for (int j = 0; j < NBLK; j++) {
        int k = j * 64 + t;
        float w;
        if (j == Bq)        w = p[j];
        else if (t == 63)   w = 0.f;
        else                w = p[j] * lm[j];
        row[k] = w;
    }
}

// ---------------- PV (stores tf32-rounded output for the Wo GEMM) ----------------
__global__ __launch_bounds__(256)
void pv_kernel()
{
    int qt = blockIdx.x, bh = blockIdx.y;
    int q0 = qt * 64;
    const float* P = g_s + (size_t)bh * SEQ * SEQ;
    const float* V = g_v + (size_t)bh * SEQ * HDIM;
    __shared__ float Ps[64][33];
    __shared__ float Vs[32][128];
    int tid = threadIdx.x, tx = tid & 15, ty = tid >> 4;
    float acc[4][8];
    #pragma unroll
    for (int i = 0; i < 4; i++)
        #pragma unroll
        for (int j = 0; j < 8; j++) acc[i][j] = 0.f;

    for (int k0 = 0; k0 < SEQ; k0 += 32) {
        #pragma unroll
        for (int i = 0; i < 2; i++) {
            int slot = tid + i * 256;
            int row = slot >> 3;
            int c4  = slot & 7;
            float4 v = *(const float4*)&P[(size_t)(q0 + row) * SEQ + k0 + c4 * 4];
            Ps[row][c4*4+0]=v.x; Ps[row][c4*4+1]=v.y; Ps[row][c4*4+2]=v.z; Ps[row][c4*4+3]=v.w;
        }
        #pragma unroll
        for (int i = 0; i < 4; i++) {
            int slot = tid + i * 256;
            int row = slot >> 5;
            int c4  = slot & 31;
            *(float4*)&Vs[row][c4*4] = *(const float4*)&V[(size_t)(k0 + row) * HDIM + c4 * 4];
        }
        __syncthreads();
        #pragma unroll
        for (int kk = 0; kk < 32; kk++) {
            float rp[4], rv[8];
            #pragma unroll
            for (int i = 0; i < 4; i++) rp[i] = Ps[ty*4+i][kk];
            *(float4*)&rv[0] = *(const float4*)&Vs[kk][tx*8];
            *(float4*)&rv[4] = *(const float4*)&Vs[kk][tx*8+4];
            #pragma unroll
            for (int i = 0; i < 4; i++)
                #pragma unroll
                for (int j = 0; j < 8; j++)
                    acc[i][j] = fmaf(rp[i], rv[j], acc[i][j]);
        }
        __syncthreads();
    }
    int b = bh >> 5, h = bh & 31;
    #pragma unroll
    for (int i = 0; i < 4; i++) {
        int qq = q0 + ty * 4 + i;
        size_t obase = ((size_t)(b * SEQ + qq)) * HID + h * HDIM + tx * 8;
        uint4 lo = { f2tf(acc[i][0]), f2tf(acc[i][1]), f2tf(acc[i][2]), f2tf(acc[i][3]) };
        uint4 hi = { f2tf(acc[i][4]), f2tf(acc[i][5]), f2tf(acc[i][6]), f2tf(acc[i][7]) };
        *(uint4*)&g_o[obase]     = lo;
        *(uint4*)&g_o[obase + 4] = hi;
    }
}

// ---------------- launch ----------------
extern "C" void kernel_launch(void* const* d_in, const int* in_sizes, int n_in,
                              void* d_out, int out_size)
{
    const float* X  = (const float*)d_in[0];
    const float* wq = (const float*)d_in[1];
    const float* wk = (const float*)d_in[2];
    const float* wv = (const float*)d_in[3];
    const float* wo = (const float*)d_in[4];
    float* out = (float*)d_out;

    static int init_done = 0;
    if (!init_done) {
        cudaFuncSetAttribute(tgemm<0>, cudaFuncAttributeMaxDynamicSharedMemorySize, TG_SMEM);
        cudaFuncSetAttribute(tgemm<1>, cudaFuncAttributeMaxDynamicSharedMemorySize, TG_SMEM);
        init_done = 1;
    }

    float* wtBase; cudaGetSymbolAddress((void**)&wtBase, g_wt);
    float* xtBase; cudaGetSymbolAddress((void**)&xtBase, g_xt);
    float* otBase; cudaGetSymbolAddress((void**)&otBase, g_ot);
    float* oBase;  cudaGetSymbolAddress((void**)&oBase,  g_o);
    const float* wT[4] = { wtBase, wtBase + (size_t)HID*HID,
                           wtBase + 2*(size_t)HID*HID, wtBase + 3*(size_t)HID*HID };

    pack_a<<<dim3(HID/32, MTOT/128), 256>>>(X, xtBase);
    pack_b<<<dim3(HID/128, HID/32, 4), 256>>>(wq, wk, wv, wo);

    dim3 gp(HID / 128, MTOT / 128);   // (32, 15)
    tgemm<1><<<gp, 256, TG_SMEM>>>(xtBase, wT[0], nullptr, 0);
    tgemm<1><<<gp, 256, TG_SMEM>>>(xtBase, wT[1], nullptr, 1);
    tgemm<1><<<gp, 256, TG_SMEM>>>(xtBase, wT[2], nullptr, 2);
    rope_kernel<<<dim3(SEQ, BHTOT), 128>>>();
    scores_kernel<<<dim3(NBLK, NBLK, BHTOT), 256>>>();
    lsoftmax_kernel<<<dim3(SEQ, BHTOT), 64>>>();
    pv_kernel<<<dim3(NBLK, BHTOT), 256>>>();
    pack_a<<<dim3(HID/32, MTOT/128), 256>>>(oBase, otBase);
    tgemm<0><<<gp, 256, TG_SMEM>>>(otBase, wT[3], out, 0);
}